// round 3
// baseline (speedup 1.0000x reference)
#include <cuda_runtime.h>
#include <cuda_bf16.h>

// MLLoss: per-sample hinge loss over [B, 16] f32 distances -> scalar mean.
// Labels are int32 (JAX x64 disabled). HBM-bound: 288 MB read.
//
// R3 changes vs R2 (51.7us, DRAM 78.5%):
//  - single kernel: last-block finalization replaces the zero_out launch
//  - 2 rows per thread per iteration -> 8 float4 + 2x int2 loads in flight
//    (higher MLP_eff to close the DRAM% gap)

#define THREADS 256
#define BLOCKS  2048

__device__ float        g_partial;   // zero-init at load; reset by last block each call
__device__ unsigned int g_count;

__device__ __forceinline__ float row_loss(const float4 a, const float4 b,
                                          const float4 c, const float4 d,
                                          const int dl, const int rl)
{
    const float h0 = fmaxf(1.0f - a.x, 0.0f);
    const float h1 = fmaxf(1.0f - a.y, 0.0f);
    float hs = h0 + h1
             + fmaxf(1.0f - a.z, 0.0f) + fmaxf(1.0f - a.w, 0.0f)
             + fmaxf(1.0f - b.x, 0.0f) + fmaxf(1.0f - b.y, 0.0f)
             + fmaxf(1.0f - b.z, 0.0f) + fmaxf(1.0f - b.w, 0.0f)
             + fmaxf(1.0f - c.x, 0.0f) + fmaxf(1.0f - c.y, 0.0f)
             + fmaxf(1.0f - c.z, 0.0f) + fmaxf(1.0f - c.w, 0.0f)
             + fmaxf(1.0f - d.x, 0.0f) + fmaxf(1.0f - d.y, 0.0f)
             + fmaxf(1.0f - d.z, 0.0f) + fmaxf(1.0f - d.w, 0.0f);

    const float loss_control   = a.x + hs - h0;
    const float loss_parkinson = a.y + hs - h1;
    const float loss_unknown   = (rl == 0) ? h1 : h0;

    return (dl == 0) ? loss_control
         : (dl == 1) ? loss_parkinson
                     : loss_unknown;
}

__global__ __launch_bounds__(THREADS)
void mlloss_kernel(const float4* __restrict__ dist4,  // [B,16] f32 as B*4 float4
                   const int2* __restrict__ doctor2,  // [B/2] int2 (int32 labels)
                   const int2* __restrict__ real2,    // [B/2]
                   float* __restrict__ out,
                   int Bpairs,                        // B / 2
                   float inv_B)
{
    const int tid    = blockIdx.x * blockDim.x + threadIdx.x;
    const int stride = gridDim.x * blockDim.x;

    float acc = 0.0f;

    // each iteration handles 2 consecutive rows (128 B of distances)
    for (int p = tid; p < Bpairs; p += stride) {
        const size_t base = (size_t)p * 8;
        const float4 a0 = dist4[base + 0];
        const float4 b0 = dist4[base + 1];
        const float4 c0 = dist4[base + 2];
        const float4 d0 = dist4[base + 3];
        const float4 a1 = dist4[base + 4];
        const float4 b1 = dist4[base + 5];
        const float4 c1 = dist4[base + 6];
        const float4 d1 = dist4[base + 7];
        const int2 dl = doctor2[p];
        const int2 rl = real2[p];

        acc += row_loss(a0, b0, c0, d0, dl.x, rl.x);
        acc += row_loss(a1, b1, c1, d1, dl.y, rl.y);
    }

    // warp reduce
    #pragma unroll
    for (int off = 16; off > 0; off >>= 1)
        acc += __shfl_xor_sync(0xFFFFFFFFu, acc, off);

    __shared__ float warp_sums[THREADS / 32];
    const int lane = threadIdx.x & 31;
    const int wid  = threadIdx.x >> 5;
    if (lane == 0) warp_sums[wid] = acc;
    __syncthreads();

    if (wid == 0) {
        float v = (lane < THREADS / 32) ? warp_sums[lane] : 0.0f;
        #pragma unroll
        for (int off = 16; off > 0; off >>= 1)
            v += __shfl_xor_sync(0xFFFFFFFFu, v, off);

        if (lane == 0) {
            atomicAdd(&g_partial, v);
            __threadfence();
            const unsigned int ticket = atomicAdd(&g_count, 1u);
            if (ticket == gridDim.x - 1) {
                // last block: finalize and reset state for the next graph replay
                const float total = atomicAdd(&g_partial, 0.0f); // fenced read
                out[0] = total * inv_B;
                g_partial = 0.0f;
                g_count   = 0u;
                __threadfence();
            }
        }
    }
}

extern "C" void kernel_launch(void* const* d_in, const int* in_sizes, int n_in,
                              void* d_out, int out_size)
{
    const float4* dist4   = (const float4*)d_in[0];
    const int2*   doctor2 = (const int2*)d_in[1];
    const int2*   real2   = (const int2*)d_in[2];
    float*        out     = (float*)d_out;

    const int B = in_sizes[1];
    const float inv_B = 1.0f / (float)B;

    mlloss_kernel<<<BLOCKS, THREADS>>>(dist4, doctor2, real2, out, B / 2, inv_B);
}

// round 4
// speedup vs baseline: 1.2463x; 1.2463x over previous
#include <cuda_runtime.h>
#include <cuda_bf16.h>

// MLLoss: per-sample hinge loss over [B, 16] f32 distances -> scalar mean.
// Labels int32. HBM-bound: 288 MB read.
//
// R4: perfectly coalesced distance loads. A warp loads 32 consecutive float4
// (512B contiguous -> 4 cache lines per LDG.128, fully used). Each 4-lane
// group owns one row; shfl_xor(1),shfl_xor(2) form the row hinge sum; group
// leader applies the label-dependent select. Labels loaded coalesced per
// 32-row chunk and routed by shuffle. Single kernel, last-block finalize.

#define THREADS 256
#define BLOCKS  2048

__device__ float        g_partial;   // zero at load; reset by last block each call
__device__ unsigned int g_count;

__global__ __launch_bounds__(THREADS)
void mlloss_kernel(const float4* __restrict__ dist4,  // [B,16] as B*4 float4
                   const int* __restrict__ doctor,    // [B] int32 {0,1,2}
                   const int* __restrict__ real_l,    // [B] int32 {0,1}
                   float* __restrict__ out,
                   int B, float inv_B)
{
    const int lane      = threadIdx.x & 31;
    const int warp_id   = (blockIdx.x * blockDim.x + threadIdx.x) >> 5;
    const int num_warps = (gridDim.x * blockDim.x) >> 5;
    const int nchunks   = B >> 5;            // 32 rows per chunk

    float acc = 0.0f;

    for (int chunk = warp_id; chunk < nchunks; chunk += num_warps) {
        const int row_base = chunk << 5;     // 32 rows
        const int f4_base  = row_base << 2;  // 128 float4 = 2 KB contiguous

        // front-batch all loads (labels coalesced: 128B per array)
        const int dl_all = doctor[row_base + lane];
        const int rl_all = real_l[row_base + lane];
        float4 v[4];
        #pragma unroll
        for (int u = 0; u < 4; u++)
            v[u] = dist4[f4_base + u * 32 + lane];

        #pragma unroll
        for (int u = 0; u < 4; u++) {
            // partial hinge sum of this thread's quarter-row
            float s = fmaxf(1.0f - v[u].x, 0.0f) + fmaxf(1.0f - v[u].y, 0.0f)
                    + fmaxf(1.0f - v[u].z, 0.0f) + fmaxf(1.0f - v[u].w, 0.0f);
            // full row hinge sum within the 4-lane group
            s += __shfl_xor_sync(0xFFFFFFFFu, s, 1);
            s += __shfl_xor_sync(0xFFFFFFFFu, s, 2);

            // row handled by this 4-lane group (within chunk): u*8 + lane/4
            const int rr = u * 8 + (lane >> 2);
            const int dl = __shfl_sync(0xFFFFFFFFu, dl_all, rr);
            const int rl = __shfl_sync(0xFFFFFFFFu, rl_all, rr);

            if ((lane & 3) == 0) {           // group leader holds cols 0..3
                const float h0 = fmaxf(1.0f - v[u].x, 0.0f);
                const float h1 = fmaxf(1.0f - v[u].y, 0.0f);
                const float lc = v[u].x + s - h0;      // doctor == 0
                const float lp = v[u].y + s - h1;      // doctor == 1
                const float lu = (rl == 0) ? h1 : h0;  // doctor == 2
                acc += (dl == 0) ? lc : (dl == 1) ? lp : lu;
            }
        }
    }

    // tail rows (B % 32) — handled scalar by first threads of block 0
    const int tail_start = nchunks << 5;
    if (blockIdx.x == 0) {
        for (int row = tail_start + threadIdx.x; row < B; row += blockDim.x) {
            const size_t base = (size_t)row * 4;
            const float4 a = dist4[base + 0], b = dist4[base + 1];
            const float4 c = dist4[base + 2], d = dist4[base + 3];
            const float h0 = fmaxf(1.0f - a.x, 0.0f);
            const float h1 = fmaxf(1.0f - a.y, 0.0f);
            float hs = h0 + h1
                     + fmaxf(1.0f - a.z, 0.0f) + fmaxf(1.0f - a.w, 0.0f)
                     + fmaxf(1.0f - b.x, 0.0f) + fmaxf(1.0f - b.y, 0.0f)
                     + fmaxf(1.0f - b.z, 0.0f) + fmaxf(1.0f - b.w, 0.0f)
                     + fmaxf(1.0f - c.x, 0.0f) + fmaxf(1.0f - c.y, 0.0f)
                     + fmaxf(1.0f - c.z, 0.0f) + fmaxf(1.0f - c.w, 0.0f)
                     + fmaxf(1.0f - d.x, 0.0f) + fmaxf(1.0f - d.y, 0.0f)
                     + fmaxf(1.0f - d.z, 0.0f) + fmaxf(1.0f - d.w, 0.0f);
            const int dl = doctor[row], rl = real_l[row];
            const float lu = (rl == 0) ? h1 : h0;
            acc += (dl == 0) ? (a.x + hs - h0)
                 : (dl == 1) ? (a.y + hs - h1) : lu;
        }
    }

    // warp reduce
    #pragma unroll
    for (int off = 16; off > 0; off >>= 1)
        acc += __shfl_xor_sync(0xFFFFFFFFu, acc, off);

    __shared__ float warp_sums[THREADS / 32];
    const int wid = threadIdx.x >> 5;
    if (lane == 0) warp_sums[wid] = acc;
    __syncthreads();

    if (wid == 0) {
        float vsum = (lane < THREADS / 32) ? warp_sums[lane] : 0.0f;
        #pragma unroll
        for (int off = 16; off > 0; off >>= 1)
            vsum += __shfl_xor_sync(0xFFFFFFFFu, vsum, off);

        if (lane == 0) {
            atomicAdd(&g_partial, vsum);
            __threadfence();
            const unsigned int ticket = atomicAdd(&g_count, 1u);
            if (ticket == gridDim.x - 1) {
                const float total = atomicAdd(&g_partial, 0.0f); // fenced read
                out[0] = total * inv_B;
                g_partial = 0.0f;
                g_count   = 0u;
                __threadfence();
            }
        }
    }
}

extern "C" void kernel_launch(void* const* d_in, const int* in_sizes, int n_in,
                              void* d_out, int out_size)
{
    const float4* dist4  = (const float4*)d_in[0];
    const int*    doctor = (const int*)d_in[1];
    const int*    real_l = (const int*)d_in[2];
    float*        out    = (float*)d_out;

    const int B = in_sizes[1];
    const float inv_B = 1.0f / (float)B;

    mlloss_kernel<<<BLOCKS, THREADS>>>(dist4, doctor, real_l, out, B, inv_B);
}